// round 2
// baseline (speedup 1.0000x reference)
#include <cuda_runtime.h>
#include <cuda_bf16.h>
#include <cstdint>

// ============================================================
// Problem: LSTMCell  B=8192, I=1024, H=1024, C=2048, 4H=4096
// gates = [x|h] @ W_stacked^T ; activations ; out = [h_t | c_t]
// Strategy: split-bf16 (hi+lo) GEMM via mma.sync (sm_103 baseline
// PTX; tcgen05 is unavailable because harness targets compute_103).
// ============================================================
#define B_DIM 8192
#define H_DIM 1024
#define C_DIM 2048
#define G_DIM 4096

// Scratch in device bss (no allocation APIs)
__device__ __nv_bfloat16 g_Ahi[(size_t)B_DIM * C_DIM];
__device__ __nv_bfloat16 g_Alo[(size_t)B_DIM * C_DIM];
__device__ __nv_bfloat16 g_Whi[(size_t)G_DIM * C_DIM];
__device__ __nv_bfloat16 g_Wlo[(size_t)G_DIM * C_DIM];
__device__ float         g_gates[(size_t)B_DIM * G_DIM];

// ============================================================
// PTX helpers (all sm_80-baseline features; legal on sm_103)
// ============================================================
__device__ __forceinline__ uint32_t smem_to_u32(const void* p) {
    uint32_t a;
    asm("{ .reg .u64 t; cvta.to.shared.u64 t, %1; cvt.u32.u64 %0, t; }" : "=r"(a) : "l"(p));
    return a;
}

__device__ __forceinline__ void cp_async16(uint32_t saddr, const void* gaddr) {
    asm volatile("cp.async.cg.shared.global [%0], [%1], 16;" :: "r"(saddr), "l"(gaddr));
}
#define CP_COMMIT() asm volatile("cp.async.commit_group;" ::: "memory")
#define CP_WAIT3()  asm volatile("cp.async.wait_group 3;" ::: "memory")

__device__ __forceinline__ void ldsm4(uint32_t& r0, uint32_t& r1, uint32_t& r2, uint32_t& r3,
                                      uint32_t addr) {
    asm volatile("ldmatrix.sync.aligned.m8n8.x4.shared.b16 {%0,%1,%2,%3}, [%4];"
                 : "=r"(r0), "=r"(r1), "=r"(r2), "=r"(r3) : "r"(addr));
}

__device__ __forceinline__ void mma_bf16(float* c, const uint32_t* a, uint32_t b0, uint32_t b1) {
    asm volatile(
        "mma.sync.aligned.m16n8k16.row.col.f32.bf16.bf16.f32 "
        "{%0,%1,%2,%3}, {%4,%5,%6,%7}, {%8,%9}, {%0,%1,%2,%3};"
        : "+f"(c[0]), "+f"(c[1]), "+f"(c[2]), "+f"(c[3])
        : "r"(a[0]), "r"(a[1]), "r"(a[2]), "r"(a[3]), "r"(b0), "r"(b1));
}

// ============================================================
// Prepass: split-bf16 of A = [x|h] and stacked W
// ============================================================
__global__ void prep_A_kernel(const float* __restrict__ x, const float* __restrict__ h) {
    size_t idx = (size_t)blockIdx.x * blockDim.x + threadIdx.x;
    if (idx >= (size_t)B_DIM * C_DIM) return;
    size_t r = idx >> 11;
    int    k = (int)(idx & 2047);
    float v = (k < 1024) ? x[r * 1024 + k] : h[r * 1024 + (k - 1024)];
    __nv_bfloat16 hi = __float2bfloat16(v);
    g_Ahi[idx] = hi;
    g_Alo[idx] = __float2bfloat16(v - __bfloat162float(hi));
}

__global__ void prep_W_kernel(const float* __restrict__ Wi, const float* __restrict__ Wf,
                              const float* __restrict__ Wo, const float* __restrict__ Wg) {
    size_t idx = (size_t)blockIdx.x * blockDim.x + threadIdx.x;
    if (idx >= (size_t)G_DIM * C_DIM) return;
    size_t n = idx >> 11;
    int    k = (int)(idx & 2047);
    int gate = (int)(n >> 10);
    size_t rr = n & 1023;
    const float* W = (gate == 0) ? Wi : (gate == 1) ? Wf : (gate == 2) ? Wo : Wg;
    float v = W[rr * 2048 + k];
    __nv_bfloat16 hi = __float2bfloat16(v);
    g_Whi[idx] = hi;
    g_Wlo[idx] = __float2bfloat16(v - __bfloat162float(hi));
}

// ============================================================
// GEMM: g_gates[8192,4096] = A @ W^T, split-bf16 (3 products)
// CTA 128x128, BK=32, 4-stage cp.async pipeline, 8 warps (2Mx4N)
// smem row stride = 40 halves (80B): conflict-free ldmatrix
// ============================================================
#define BM 128
#define BN 128
#define BK 32
#define STAGES 4
#define SA 40                                 // halves per smem row
#define ARR_BYTES (128 * SA * 2)              // 10240 B per tile array
#define STAGE_BYTES (4 * ARR_BYTES)           // 40960 B (Ahi,Alo,Whi,Wlo)
#define SMEM_TOTAL (STAGES * STAGE_BYTES)     // 163840 B
#define KT (C_DIM / BK)                       // 64 k-stages

__global__ void __launch_bounds__(256, 1) lstm_gemm_kernel() {
    extern __shared__ __align__(128) char smem[];
    const uint32_t sb = smem_to_u32(smem);
    const int tid = threadIdx.x;
    const int m0 = blockIdx.x * BM;   // x over M: consecutive CTAs share W tile
    const int n0 = blockIdx.y * BN;
    const int l = tid & 31, w = tid >> 5;
    const int wm = w >> 2, wn = w & 3;            // warp grid 2(M) x 4(N)

    // --- global-load decomposition: 512 16B-chunks per array per stage,
    //     2 chunks per thread per array ---
    const int c0 = tid * 2;
    const __nv_bfloat16* gA0 = g_Ahi + (size_t)m0 * C_DIM;
    const __nv_bfloat16* gA1 = g_Alo + (size_t)m0 * C_DIM;
    const __nv_bfloat16* gW0 = g_Whi + (size_t)n0 * C_DIM;
    const __nv_bfloat16* gW1 = g_Wlo + (size_t)n0 * C_DIM;

    // --- ldmatrix lane base offsets (bytes within a tile array) ---
    const uint32_t a_off = (uint32_t)((wm * 64 + (l & 15)) * SA + (l >> 4) * 8) * 2;
    const uint32_t b_off = (uint32_t)((wn * 32 + (l & 15)) * SA + (l >> 4) * 8) * 2;

    float acc[4][4][4];
#pragma unroll
    for (int i = 0; i < 4; i++)
#pragma unroll
        for (int j = 0; j < 4; j++)
#pragma unroll
            for (int r = 0; r < 4; r++) acc[i][j][r] = 0.0f;

    // ---- stage loader ----
    auto load_stage = [&](int slot, int kt) {
        const int k0 = kt * BK;
        const uint32_t sbase = sb + slot * STAGE_BYTES;
#pragma unroll
        for (int j = 0; j < 2; j++) {
            const int c = c0 + j;
            const int row = c >> 2, seg = c & 3;
            const uint32_t soff = (uint32_t)(row * SA + seg * 8) * 2;
            const size_t goff = (size_t)row * C_DIM + k0 + seg * 8;
            cp_async16(sbase + 0 * ARR_BYTES + soff, gA0 + goff);
            cp_async16(sbase + 1 * ARR_BYTES + soff, gA1 + goff);
            cp_async16(sbase + 2 * ARR_BYTES + soff, gW0 + goff);
            cp_async16(sbase + 3 * ARR_BYTES + soff, gW1 + goff);
        }
    };

    // ---- prologue: fill STAGES-1 stages ----
#pragma unroll
    for (int s = 0; s < STAGES - 1; s++) {
        load_stage(s, s);
        CP_COMMIT();
    }

    // ---- main loop ----
    for (int i = 0; i < KT; i++) {
        const int pf = i + STAGES - 1;
        if (pf < KT) load_stage(pf & (STAGES - 1), pf);
        CP_COMMIT();                      // empty group when pf >= KT (keeps count uniform)
        CP_WAIT3();                       // stage i now resident
        __syncthreads();

        const uint32_t sbase = sb + (i & (STAGES - 1)) * STAGE_BYTES;
        const uint32_t aAh = sbase + 0 * ARR_BYTES + a_off;
        const uint32_t aAl = sbase + 1 * ARR_BYTES + a_off;
        const uint32_t aWh = sbase + 2 * ARR_BYTES + b_off;
        const uint32_t aWl = sbase + 3 * ARR_BYTES + b_off;

#pragma unroll
        for (int k16 = 0; k16 < 2; k16++) {
            const uint32_t kd = (uint32_t)(k16 * 16) * 2;   // 16 halves along K
            uint32_t Ah[4][4], Al[4][4], Bh[2][4], Bl[2][4];
#pragma unroll
            for (int mt = 0; mt < 4; mt++) {
                const uint32_t md = (uint32_t)(mt * 16 * SA) * 2;
                ldsm4(Ah[mt][0], Ah[mt][1], Ah[mt][2], Ah[mt][3], aAh + md + kd);
                ldsm4(Al[mt][0], Al[mt][1], Al[mt][2], Al[mt][3], aAl + md + kd);
            }
#pragma unroll
            for (int ntp = 0; ntp < 2; ntp++) {
                const uint32_t nd = (uint32_t)(ntp * 16 * SA) * 2;
                ldsm4(Bh[ntp][0], Bh[ntp][1], Bh[ntp][2], Bh[ntp][3], aWh + nd + kd);
                ldsm4(Bl[ntp][0], Bl[ntp][1], Bl[ntp][2], Bl[ntp][3], aWl + nd + kd);
            }
#pragma unroll
            for (int mt = 0; mt < 4; mt++) {
#pragma unroll
                for (int nt = 0; nt < 4; nt++) {
                    const int p = nt >> 1, q = nt & 1;
                    // hi*hi + hi*lo + lo*hi  (lo*lo term ~2^-16 rel: dropped)
                    mma_bf16(acc[mt][nt], Ah[mt], Bh[p][q], Bh[p][q + 2]);
                    mma_bf16(acc[mt][nt], Ah[mt], Bl[p][q], Bl[p][q + 2]);
                    mma_bf16(acc[mt][nt], Al[mt], Bh[p][q], Bh[p][q + 2]);
                }
            }
        }
        __syncthreads();                  // protect slot reuse by next iteration's loads
    }

    // ---- epilogue: write fp32 gates ----
#pragma unroll
    for (int mt = 0; mt < 4; mt++) {
        const int row0 = m0 + wm * 64 + mt * 16 + (l >> 2);
#pragma unroll
        for (int nt = 0; nt < 4; nt++) {
            const int col = n0 + wn * 32 + nt * 8 + (l & 3) * 2;
            float2* p0 = (float2*)(g_gates + (size_t)row0 * G_DIM + col);
            float2* p1 = (float2*)(g_gates + (size_t)(row0 + 8) * G_DIM + col);
            *p0 = make_float2(acc[mt][nt][0], acc[mt][nt][1]);
            *p1 = make_float2(acc[mt][nt][2], acc[mt][nt][3]);
        }
    }
}

// ============================================================
// Fused LSTM activation epilogue
// ============================================================
__global__ void lstm_act_kernel(const float* __restrict__ c,
                                const float* __restrict__ bi, const float* __restrict__ bf_,
                                const float* __restrict__ bo, const float* __restrict__ bg,
                                float* __restrict__ out) {
    size_t idx = (size_t)blockIdx.x * blockDim.x + threadIdx.x;
    if (idx >= (size_t)B_DIM * H_DIM) return;
    int j = (int)(idx & (H_DIM - 1));
    size_t row = idx >> 10;
    const float* g = g_gates + row * G_DIM;
    float ip = g[j]        + bi[j];
    float fp = g[j + 1024] + bf_[j];
    float op = g[j + 2048] + bo[j];
    float gp = g[j + 3072] + bg[j];
    float iv = 1.0f / (1.0f + __expf(-ip));
    float fv = 1.0f / (1.0f + __expf(-fp));
    float ov = 1.0f / (1.0f + __expf(-op));
    float gv = tanhf(gp);
    float ct = fv * c[idx] + iv * gv;
    float ht = ov * tanhf(ct);
    out[idx] = ht;                                 // h_t
    out[(size_t)B_DIM * H_DIM + idx] = ct;         // c_t
}

// ============================================================
// kernel_launch
// Inputs: x, h, c, W_i, W_f, W_o, W_g, b_i, b_f, b_o, b_g
// Output: [h_t (B*H) | c_t (B*H)] fp32
// ============================================================
extern "C" void kernel_launch(void* const* d_in, const int* in_sizes, int n_in,
                              void* d_out, int out_size) {
    const float* x  = (const float*)d_in[0];
    const float* h  = (const float*)d_in[1];
    const float* c  = (const float*)d_in[2];
    const float* Wi = (const float*)d_in[3];
    const float* Wf = (const float*)d_in[4];
    const float* Wo = (const float*)d_in[5];
    const float* Wg = (const float*)d_in[6];
    const float* bi = (const float*)d_in[7];
    const float* bf_ = (const float*)d_in[8];
    const float* bo = (const float*)d_in[9];
    const float* bg = (const float*)d_in[10];
    float* out = (float*)d_out;

    cudaFuncSetAttribute(lstm_gemm_kernel,
                         cudaFuncAttributeMaxDynamicSharedMemorySize, SMEM_TOTAL);

    {   // prepass A
        size_t n = (size_t)B_DIM * C_DIM;
        prep_A_kernel<<<(unsigned)((n + 255) / 256), 256>>>(x, h);
    }
    {   // prepass W
        size_t n = (size_t)G_DIM * C_DIM;
        prep_W_kernel<<<(unsigned)((n + 255) / 256), 256>>>(Wi, Wf, Wo, Wg);
    }
    {   // GEMM: grid x over M (64), y over N (32)
        dim3 grid(B_DIM / BM, G_DIM / BN);
        lstm_gemm_kernel<<<grid, 256, SMEM_TOTAL>>>();
    }
    {   // activations
        size_t n = (size_t)B_DIM * H_DIM;
        lstm_act_kernel<<<(unsigned)((n + 255) / 256), 256>>>(c, bi, bf_, bo, bg, out);
    }
}

// round 3
// speedup vs baseline: 1.6751x; 1.6751x over previous
#include <cuda_runtime.h>
#include <cuda_fp16.h>
#include <cstdint>

// ============================================================
// LSTMCell: B=8192, I=1024, H=1024, C=2048, 4H=4096
// gates = [x|h] @ W^T (+b); activations fused into GEMM epilogue.
// Single-pass fp16 mma.sync (SIMT HMMA pipe is the binder: rt16,
// 512 MACs/cyc/SM). W stored gate-interleaved: row p = 4*j + gate,
// so one 128-wide N tile = 32 h-columns x 4 gates.
// ============================================================
#define B_DIM 8192
#define H_DIM 1024
#define C_DIM 2048
#define G_DIM 4096

__device__ __half g_A[(size_t)B_DIM * C_DIM];   // [x|h] fp16
__device__ __half g_W[(size_t)G_DIM * C_DIM];   // permuted stacked W fp16

// ============================================================
// PTX helpers (sm_80-baseline; legal at compute_103)
// ============================================================
__device__ __forceinline__ uint32_t smem_to_u32(const void* p) {
    uint32_t a;
    asm("{ .reg .u64 t; cvta.to.shared.u64 t, %1; cvt.u32.u64 %0, t; }" : "=r"(a) : "l"(p));
    return a;
}
__device__ __forceinline__ void cp_async16(uint32_t saddr, const void* gaddr) {
    asm volatile("cp.async.cg.shared.global [%0], [%1], 16;" :: "r"(saddr), "l"(gaddr));
}
#define CP_COMMIT() asm volatile("cp.async.commit_group;" ::: "memory")
#define CP_WAIT3()  asm volatile("cp.async.wait_group 3;" ::: "memory")

__device__ __forceinline__ void ldsm4(uint32_t& r0, uint32_t& r1, uint32_t& r2, uint32_t& r3,
                                      uint32_t addr) {
    asm volatile("ldmatrix.sync.aligned.m8n8.x4.shared.b16 {%0,%1,%2,%3}, [%4];"
                 : "=r"(r0), "=r"(r1), "=r"(r2), "=r"(r3) : "r"(addr));
}
__device__ __forceinline__ void mma_fp16(float* c, const uint32_t* a, uint32_t b0, uint32_t b1) {
    asm volatile(
        "mma.sync.aligned.m16n8k16.row.col.f32.f16.f16.f32 "
        "{%0,%1,%2,%3}, {%4,%5,%6,%7}, {%8,%9}, {%0,%1,%2,%3};"
        : "+f"(c[0]), "+f"(c[1]), "+f"(c[2]), "+f"(c[3])
        : "r"(a[0]), "r"(a[1]), "r"(a[2]), "r"(a[3]), "r"(b0), "r"(b1));
}

// ============================================================
// Prepasses
// ============================================================
__global__ void prep_A_kernel(const float* __restrict__ x, const float* __restrict__ h) {
    size_t idx = (size_t)blockIdx.x * blockDim.x + threadIdx.x;
    if (idx >= (size_t)B_DIM * C_DIM) return;
    size_t r = idx >> 11;
    int    k = (int)(idx & 2047);
    float v = (k < 1024) ? x[r * 1024 + k] : h[r * 1024 + (k - 1024)];
    g_A[idx] = __float2half_rn(v);
}

// permuted: row p = 4*j + gate  (gate: 0=i,1=f,2=o,3=g)
__global__ void prep_W_kernel(const float* __restrict__ Wi, const float* __restrict__ Wf,
                              const float* __restrict__ Wo, const float* __restrict__ Wg) {
    size_t idx = (size_t)blockIdx.x * blockDim.x + threadIdx.x;
    if (idx >= (size_t)G_DIM * C_DIM) return;
    size_t p = idx >> 11;
    int    k = (int)(idx & 2047);
    int gate = (int)(p & 3);
    size_t j = p >> 2;
    const float* W = (gate == 0) ? Wi : (gate == 1) ? Wf : (gate == 2) ? Wo : Wg;
    g_W[idx] = __float2half_rn(W[j * 2048 + k]);
}

// ============================================================
// GEMM + fused LSTM epilogue
// CTA 128x128, BK=32, 4-stage cp.async, 8 warps (2M x 4N)
// ============================================================
#define BM 128
#define BN 128
#define BK 32
#define STAGES 4
#define SA 40                                  // halves per smem row (conflict-free ldmatrix)
#define ARR_BYTES (128 * SA * 2)               // 10240
#define STAGE_BYTES (2 * ARR_BYTES)            // A + W
#define SMEM_TOTAL (STAGES * STAGE_BYTES)      // 81920
#define KT (C_DIM / BK)                        // 64
#define SROW 132                               // epilogue smem stride (floats)

__global__ void __launch_bounds__(256, 1) lstm_gemm_kernel(
    const float* __restrict__ cin,
    const float* __restrict__ bi, const float* __restrict__ bf_,
    const float* __restrict__ bo, const float* __restrict__ bg,
    float* __restrict__ out)
{
    extern __shared__ __align__(128) char smem[];
    const uint32_t sb = smem_to_u32(smem);
    const int tid = threadIdx.x;
    const int m0 = blockIdx.x * BM;
    const int n0 = blockIdx.y * BN;            // permuted-gate column block
    const int l = tid & 31, w = tid >> 5;
    const int wm = w >> 2, wn = w & 3;         // 2(M) x 4(N) warps

    const __half* gA = g_A + (size_t)m0 * C_DIM;
    const __half* gW = g_W + (size_t)n0 * C_DIM;

    const uint32_t a_off = (uint32_t)((wm * 64 + (l & 15)) * SA + (l >> 4) * 8) * 2;
    const uint32_t b_off = (uint32_t)((wn * 32 + (l & 15)) * SA + (l >> 4) * 8) * 2;

    float acc[4][4][4];
#pragma unroll
    for (int i = 0; i < 4; i++)
#pragma unroll
        for (int j = 0; j < 4; j++)
#pragma unroll
            for (int r = 0; r < 4; r++) acc[i][j][r] = 0.0f;

    const int c0 = tid * 2;
    auto load_stage = [&](int slot, int kt) {
        const int k0 = kt * BK;
        const uint32_t sbase = sb + slot * STAGE_BYTES;
#pragma unroll
        for (int j = 0; j < 2; j++) {
            const int cc = c0 + j;
            const int row = cc >> 2, seg = cc & 3;
            const uint32_t soff = (uint32_t)(row * SA + seg * 8) * 2;
            const size_t goff = (size_t)row * C_DIM + k0 + seg * 8;
            cp_async16(sbase + soff, gA + goff);
            cp_async16(sbase + ARR_BYTES + soff, gW + goff);
        }
    };

#pragma unroll
    for (int s = 0; s < STAGES - 1; s++) { load_stage(s, s); CP_COMMIT(); }

    for (int i = 0; i < KT; i++) {
        const int pf = i + STAGES - 1;
        if (pf < KT) load_stage(pf & (STAGES - 1), pf);
        CP_COMMIT();
        CP_WAIT3();
        __syncthreads();

        const uint32_t sbase = sb + (i & (STAGES - 1)) * STAGE_BYTES;
        const uint32_t aA = sbase + a_off;
        const uint32_t aW = sbase + ARR_BYTES + b_off;

#pragma unroll
        for (int k16 = 0; k16 < 2; k16++) {
            const uint32_t kd = (uint32_t)(k16 * 16) * 2;
            uint32_t Af[4][4], Bf[2][4];
#pragma unroll
            for (int mt = 0; mt < 4; mt++) {
                const uint32_t md = (uint32_t)(mt * 16 * SA) * 2;
                ldsm4(Af[mt][0], Af[mt][1], Af[mt][2], Af[mt][3], aA + md + kd);
            }
#pragma unroll
            for (int ntp = 0; ntp < 2; ntp++) {
                const uint32_t nd = (uint32_t)(ntp * 16 * SA) * 2;
                ldsm4(Bf[ntp][0], Bf[ntp][1], Bf[ntp][2], Bf[ntp][3], aW + nd + kd);
            }
#pragma unroll
            for (int mt = 0; mt < 4; mt++)
#pragma unroll
                for (int nt = 0; nt < 4; nt++) {
                    const int p = nt >> 1, q = nt & 1;
                    mma_fp16(acc[mt][nt], Af[mt], Bf[p][q], Bf[p][q + 2]);
                }
        }
        __syncthreads();
    }

    // ---- fused epilogue: smem transpose -> activations -> out ----
    float* sout = (float*)smem;                // reuse pipeline smem (67.6KB <= 80KB)
#pragma unroll
    for (int mt = 0; mt < 4; mt++) {
        const int row0 = wm * 64 + mt * 16 + (l >> 2);
#pragma unroll
        for (int nt = 0; nt < 4; nt++) {
            const int col = wn * 32 + nt * 8 + (l & 3) * 2;
            *(float2*)&sout[(size_t)row0 * SROW + col] =
                make_float2(acc[mt][nt][0], acc[mt][nt][1]);
            *(float2*)&sout[(size_t)(row0 + 8) * SROW + col] =
                make_float2(acc[mt][nt][2], acc[mt][nt][3]);
        }
    }
    __syncthreads();

    const int jl = tid & 31;                   // local h-column 0..31
    const int rbase = tid >> 5;                // 8 row groups
    const int jg = (n0 >> 2) + jl;             // global h-column
    const float Bi = bi[jg], Bff = bf_[jg], Bo = bo[jg], Bg = bg[jg];

#pragma unroll
    for (int rep = 0; rep < 16; rep++) {
        const int row = rbase + rep * 8;
        float4 q = *(float4*)&sout[(size_t)row * SROW + 4 * jl];
        const float ip = q.x + Bi;
        const float fp = q.y + Bff;
        const float op = q.z + Bo;
        const float gp = q.w + Bg;
        const float iv = 1.0f / (1.0f + __expf(-ip));
        const float fv = 1.0f / (1.0f + __expf(-fp));
        const float ov = 1.0f / (1.0f + __expf(-op));
        const float gv = 1.0f - 2.0f / (__expf(2.0f * gp) + 1.0f);
        const size_t gidx = (size_t)(m0 + row) * H_DIM + jg;
        const float ct = fv * cin[gidx] + iv * gv;
        const float th = 1.0f - 2.0f / (__expf(2.0f * ct) + 1.0f);
        out[gidx] = ov * th;                                   // h_t
        out[(size_t)B_DIM * H_DIM + gidx] = ct;                // c_t
    }
}

// ============================================================
// kernel_launch
// Inputs: x, h, c, W_i, W_f, W_o, W_g, b_i, b_f, b_o, b_g
// Output: [h_t (B*H) | c_t (B*H)] fp32
// ============================================================
extern "C" void kernel_launch(void* const* d_in, const int* in_sizes, int n_in,
                              void* d_out, int out_size) {
    const float* x  = (const float*)d_in[0];
    const float* h  = (const float*)d_in[1];
    const float* c  = (const float*)d_in[2];
    const float* Wi = (const float*)d_in[3];
    const float* Wf = (const float*)d_in[4];
    const float* Wo = (const float*)d_in[5];
    const float* Wg = (const float*)d_in[6];
    const float* bi = (const float*)d_in[7];
    const float* bf_ = (const float*)d_in[8];
    const float* bo = (const float*)d_in[9];
    const float* bg = (const float*)d_in[10];
    float* out = (float*)d_out;

    cudaFuncSetAttribute(lstm_gemm_kernel,
                         cudaFuncAttributeMaxDynamicSharedMemorySize, SMEM_TOTAL);

    {
        size_t n = (size_t)B_DIM * C_DIM;
        prep_A_kernel<<<(unsigned)((n + 255) / 256), 256>>>(x, h);
    }
    {
        size_t n = (size_t)G_DIM * C_DIM;
        prep_W_kernel<<<(unsigned)((n + 255) / 256), 256>>>(Wi, Wf, Wo, Wg);
    }
    {
        dim3 grid(B_DIM / BM, G_DIM / BN);
        lstm_gemm_kernel<<<grid, 256, SMEM_TOTAL>>>(c, bi, bf_, bo, bg, out);
    }
}

// round 5
// speedup vs baseline: 2.2169x; 1.3235x over previous
#include <cuda_runtime.h>
#include <cuda_fp16.h>
#include <cstdint>

// ============================================================
// LSTMCell: B=8192, I=1024, H=1024, C=2048, 4H=4096
// Single-pass fp16 mma.sync GEMM (tcgen05 unavailable: harness
// targets compute_103). CTA 128x256, warp tile 64x64, BK=32,
// 4-stage cp.async, one sync per ktile. W gate-interleaved
// (row p = 4*j + gate) so activations fuse into the epilogue.
// ============================================================
#define B_DIM 8192
#define H_DIM 1024
#define C_DIM 2048
#define G_DIM 4096

__device__ __half g_A[(size_t)B_DIM * C_DIM];   // [x|h] fp16
__device__ __half g_W[(size_t)G_DIM * C_DIM];   // permuted stacked W fp16

// ============================================================
// PTX helpers (sm_80-baseline; legal at compute_103)
// ============================================================
__device__ __forceinline__ uint32_t smem_to_u32(const void* p) {
    uint32_t a;
    asm("{ .reg .u64 t; cvta.to.shared.u64 t, %1; cvt.u32.u64 %0, t; }" : "=r"(a) : "l"(p));
    return a;
}
__device__ __forceinline__ void cp_async16(uint32_t saddr, const void* gaddr) {
    asm volatile("cp.async.cg.shared.global [%0], [%1], 16;" :: "r"(saddr), "l"(gaddr));
}
#define CP_COMMIT() asm volatile("cp.async.commit_group;" ::: "memory")
#define CP_WAIT2()  asm volatile("cp.async.wait_group 2;" ::: "memory")

__device__ __forceinline__ void ldsm4(uint32_t& r0, uint32_t& r1, uint32_t& r2, uint32_t& r3,
                                      uint32_t addr) {
    asm volatile("ldmatrix.sync.aligned.m8n8.x4.shared.b16 {%0,%1,%2,%3}, [%4];"
                 : "=r"(r0), "=r"(r1), "=r"(r2), "=r"(r3) : "r"(addr));
}
__device__ __forceinline__ void mma_fp16(float* c, const uint32_t* a, uint32_t b0, uint32_t b1) {
    asm volatile(
        "mma.sync.aligned.m16n8k16.row.col.f32.f16.f16.f32 "
        "{%0,%1,%2,%3}, {%4,%5,%6,%7}, {%8,%9}, {%0,%1,%2,%3};"
        : "+f"(c[0]), "+f"(c[1]), "+f"(c[2]), "+f"(c[3])
        : "r"(a[0]), "r"(a[1]), "r"(a[2]), "r"(a[3]), "r"(b0), "r"(b1));
}

__device__ __forceinline__ uint32_t h2_bits(__half2 v) {
    return *reinterpret_cast<uint32_t*>(&v);
}

// ============================================================
// Prepasses (vectorized: 8 elements / thread)
// ============================================================
__global__ void prep_A_kernel(const float* __restrict__ x, const float* __restrict__ h) {
    size_t idx = (size_t)blockIdx.x * blockDim.x + threadIdx.x;   // of B*C/8
    size_t base = idx * 8;
    size_t r = base >> 11;
    int    k = (int)(base & 2047);
    const float* src = (k < 1024) ? (x + r * 1024 + k) : (h + r * 1024 + (k - 1024));
    float4 v0 = *(const float4*)(src);
    float4 v1 = *(const float4*)(src + 4);
    uint4 o;
    o.x = h2_bits(__floats2half2_rn(v0.x, v0.y));
    o.y = h2_bits(__floats2half2_rn(v0.z, v0.w));
    o.z = h2_bits(__floats2half2_rn(v1.x, v1.y));
    o.w = h2_bits(__floats2half2_rn(v1.z, v1.w));
    *(uint4*)(g_A + base) = o;
}

// permuted: row p = 4*j + gate  (gate: 0=i,1=f,2=o,3=g)
__global__ void prep_W_kernel(const float* __restrict__ Wi, const float* __restrict__ Wf,
                              const float* __restrict__ Wo, const float* __restrict__ Wg) {
    size_t idx = (size_t)blockIdx.x * blockDim.x + threadIdx.x;   // of G*C/8
    size_t base = idx * 8;
    size_t p = base >> 11;
    int    k = (int)(base & 2047);
    int gate = (int)(p & 3);
    size_t j = p >> 2;
    const float* W = (gate == 0) ? Wi : (gate == 1) ? Wf : (gate == 2) ? Wo : Wg;
    const float* src = W + j * 2048 + k;
    float4 v0 = *(const float4*)(src);
    float4 v1 = *(const float4*)(src + 4);
    uint4 o;
    o.x = h2_bits(__floats2half2_rn(v0.x, v0.y));
    o.y = h2_bits(__floats2half2_rn(v0.z, v0.w));
    o.z = h2_bits(__floats2half2_rn(v1.x, v1.y));
    o.w = h2_bits(__floats2half2_rn(v1.z, v1.w));
    *(uint4*)(g_W + base) = o;
}

// ============================================================
// GEMM + fused LSTM epilogue
// ============================================================
#define BM 128
#define BN 256
#define BK 32
#define STAGES 4
#define SA 40                                     // halves per smem row
#define A_BYTES (BM * SA * 2)                     // 10240
#define W_BYTES (BN * SA * 2)                     // 20480
#define STAGE_BYTES (A_BYTES + W_BYTES)           // 30720
#define SMEM_TOTAL (STAGES * STAGE_BYTES)         // 122880
#define KT (C_DIM / BK)                           // 64
#define SROW 260                                  // epilogue smem stride (floats)

__global__ void __launch_bounds__(256, 1) lstm_gemm_kernel(
    const float* __restrict__ cin,
    const float* __restrict__ bi, const float* __restrict__ bf_,
    const float* __restrict__ bo, const float* __restrict__ bg,
    float* __restrict__ out)
{
    extern __shared__ __align__(128) char smem[];
    const uint32_t sb = smem_to_u32(smem);
    const int tid = threadIdx.x;
    const int m0 = blockIdx.x * BM;
    const int n0 = blockIdx.y * BN;
    const int l = tid & 31, w = tid >> 5;
    const int wm = w >> 2, wn = w & 3;            // 2(M) x 4(N); warp tile 64x64

    const __half* gA = g_A + (size_t)m0 * C_DIM;
    const __half* gW = g_W + (size_t)n0 * C_DIM;

    const uint32_t a_off = (uint32_t)((wm * 64 + (l & 15)) * SA + (l >> 4) * 8) * 2;
    const uint32_t b_off = (uint32_t)((wn * 64 + (l & 15)) * SA + (l >> 4) * 8) * 2;

    float acc[4][8][4];
#pragma unroll
    for (int i = 0; i < 4; i++)
#pragma unroll
        for (int j = 0; j < 8; j++)
#pragma unroll
            for (int r = 0; r < 4; r++) acc[i][j][r] = 0.0f;

    // A: 512 16B-chunks/stage (2/thread); W: 1024 (4/thread)
    auto load_stage = [&](int slot, int kt) {
        const int k0 = kt * BK;
        const uint32_t sbase = sb + slot * STAGE_BYTES;
#pragma unroll
        for (int j = 0; j < 2; j++) {
            const int c = tid * 2 + j;
            const int row = c >> 2, seg = c & 3;
            cp_async16(sbase + (uint32_t)(row * SA + seg * 8) * 2,
                       gA + (size_t)row * C_DIM + k0 + seg * 8);
        }
#pragma unroll
        for (int j = 0; j < 4; j++) {
            const int c = tid * 4 + j;
            const int row = c >> 2, seg = c & 3;
            cp_async16(sbase + A_BYTES + (uint32_t)(row * SA + seg * 8) * 2,
                       gW + (size_t)row * C_DIM + k0 + seg * 8);
        }
    };

#pragma unroll
    for (int s = 0; s < STAGES - 1; s++) { load_stage(s, s); CP_COMMIT(); }

    for (int i = 0; i < KT; i++) {
        CP_WAIT2();                      // stage i resident (<=2 groups in flight)
        __syncthreads();                 // also: everyone done with slot (i-1)&3 before refill
        const int pf = i + STAGES - 1;
        if (pf < KT) load_stage(pf & (STAGES - 1), pf);
        CP_COMMIT();                     // uniform group count

        const uint32_t sbase = sb + (i & (STAGES - 1)) * STAGE_BYTES;
        const uint32_t aA = sbase + a_off;
        const uint32_t aW = sbase + A_BYTES + b_off;

#pragma unroll
        for (int k16 = 0; k16 < 2; k16++) {
            const uint32_t kd = (uint32_t)(k16 * 16) * 2;
            uint32_t Af[4][4], Bf[4][4];
#pragma unroll
            for (int mt = 0; mt < 4; mt++) {
                const uint32_t md = (uint32_t)(mt * 16 * SA) * 2;
                ldsm4(Af[mt][0], Af[mt][1], Af[mt][2], Af[mt][3], aA + md + kd);
            }
#pragma unroll
            for (int ntp = 0; ntp < 4; ntp++) {
                const uint32_t nd = (uint32_t)(ntp * 16 * SA) * 2;
                ldsm4(Bf[ntp][0], Bf[ntp][1], Bf[ntp][2], Bf[ntp][3], aW + nd + kd);
            }
#pragma unroll
            for (int mt = 0; mt < 4; mt++)
#pragma unroll
                for (int nt = 0; nt < 8; nt++) {
                    const int p = nt >> 1, q = nt & 1;
                    mma_fp16(acc[mt][nt], Af[mt], Bf[p][q], Bf[p][q + 2]);
                }
        }
    }
    __syncthreads();

    // ---- fused epilogue in two 64-row halves (smem reuse) ----
    float* sout = (float*)smem;
    const int jl = tid & 63;                      // local h-col 0..63
    const int rg = tid >> 6;                      // 4 row groups
    const int jg = (n0 >> 2) + jl;                // global h-col
    const float Bi = bi[jg], Bff = bf_[jg], Bo = bo[jg], Bg = bg[jg];

#pragma unroll
    for (int half = 0; half < 2; half++) {
        if (wm == half) {
#pragma unroll
            for (int mt = 0; mt < 4; mt++) {
                const int row0 = mt * 16 + (l >> 2);          // local 0..63
#pragma unroll
                for (int nt = 0; nt < 8; nt++) {
                    const int col = wn * 64 + nt * 8 + (l & 3) * 2;
                    *(float2*)&sout[(size_t)row0 * SROW + col] =
                        make_float2(acc[mt][nt][0], acc[mt][nt][1]);
                    *(float2*)&sout[(size_t)(row0 + 8) * SROW + col] =
                        make_float2(acc[mt][nt][2], acc[mt][nt][3]);
                }
            }
        }
        __syncthreads();

#pragma unroll
        for (int rep = 0; rep < 16; rep++) {
            const int row = rg + rep * 4;                      // local 0..63
            float4 q = *(float4*)&sout[(size_t)row * SROW + 4 * jl];
            const float ip = q.x + Bi;
            const float fp = q.y + Bff;
            const float op = q.z + Bo;
            const float gp = q.w + Bg;
            const float iv = 1.0f / (1.0f + __expf(-ip));
            const float fv = 1.0f / (1.0f + __expf(-fp));
            const float ov = 1.0f / (1.0f + __expf(-op));
            const float gv = 1.0f - 2.0f / (__expf(2.0f * gp) + 1.0f);
            const size_t gidx = (size_t)(m0 + half * 64 + row) * H_DIM + jg;
            const float ct = fv * cin[gidx] + iv * gv;
            const float th = 1.0f - 2.0f / (__expf(2.0f * ct) + 1.0f);
            out[gidx] = ov * th;                               // h_t
            out[(size_t)B_DIM * H_DIM + gidx] = ct;            // c_t
        }
        __syncthreads();
    }
}

// ============================================================
// kernel_launch
// Inputs: x, h, c, W_i, W_f, W_o, W_g, b_i, b_f, b_o, b_g
// Output: [h_t (B*H) | c_t (B*H)] fp32
// ============================================================
extern "C" void kernel_launch(void* const* d_in, const int* in_sizes, int n_in,
                              void* d_out, int out_size) {
    const float* x  = (const float*)d_in[0];
    const float* h  = (const float*)d_in[1];
    const float* c  = (const float*)d_in[2];
    const float* Wi = (const float*)d_in[3];
    const float* Wf = (const float*)d_in[4];
    const float* Wo = (const float*)d_in[5];
    const float* Wg = (const float*)d_in[6];
    const float* bi = (const float*)d_in[7];
    const float* bf_ = (const float*)d_in[8];
    const float* bo = (const float*)d_in[9];
    const float* bg = (const float*)d_in[10];
    float* out = (float*)d_out;

    cudaFuncSetAttribute(lstm_gemm_kernel,
                         cudaFuncAttributeMaxDynamicSharedMemorySize, SMEM_TOTAL);

    {   // prepass A: B*C/8 vector threads
        size_t n = (size_t)B_DIM * C_DIM / 8;
        prep_A_kernel<<<(unsigned)(n / 256), 256>>>(x, h);
    }
    {   // prepass W
        size_t n = (size_t)G_DIM * C_DIM / 8;
        prep_W_kernel<<<(unsigned)(n / 256), 256>>>(Wi, Wf, Wo, Wg);
    }
    {   // GEMM + fused epilogue
        dim3 grid(B_DIM / BM, G_DIM / BN);
        lstm_gemm_kernel<<<grid, 256, SMEM_TOTAL>>>(c, bi, bf_, bo, bg, out);
    }
}